// round 11
// baseline (speedup 1.0000x reference)
#include <cuda_runtime.h>
#include <cuda_bf16.h>
#include <cstdint>

// VQ cdist: out[n,k] = sqrt(max(||x_n||^2 + ||e_k||^2 - 2 x_n.e_k, 0))
// N=65536, K=1024, D=64.  mma.sync path (tcgen05 rejected by compute_103).
//
// R11: warp-autonomous pipelines. Each warp owns a private 3-stage cp.async
// pipeline for ITS 32 A-rows (+norms); cp.async groups are per-thread so no
// __syncthreads in the main loop -> warps de-phase and epilogue (MUFU/STG)
// of one warp overlaps mainloop (LDSM/MMA) of others. B tile + es loaded once
// (plain LDG/STS, one prologue barrier), B fragments persistent in registers.
// sqrt.approx + __stcs epilogue, permuted-B placement for float4 stores.

#define BM 128
#define BN 64

#define A_ST   4224                 // per-warp stage: 4KB A slice + 128B xs + pad
#define WREG   (3 * A_ST)           // 12672 per warp
#define ES_OFF 8192                 // after B tile (8KB)
#define WBASE  8448                 // warp regions start (B 8KB + es 256B)
#define DYN_SMEM (WBASE + 8 * WREG) // 109824

#define MAXN 65536
#define MAXK 1024

__device__ __nv_bfloat16 g_Xbf[MAXN * 64];
__device__ float         g_xsq[MAXN];
__device__ __nv_bfloat16 g_Ebf[MAXK * 64];
__device__ float         g_esq[MAXK];

#define SWZ(o) ((o) ^ (((o) >> 3) & 0x70))

__device__ __forceinline__ void ldsm_x4(uint32_t& r0, uint32_t& r1, uint32_t& r2, uint32_t& r3, uint32_t addr) {
    asm volatile("ldmatrix.sync.aligned.m8n8.x4.shared.b16 {%0,%1,%2,%3}, [%4];"
                 : "=r"(r0), "=r"(r1), "=r"(r2), "=r"(r3) : "r"(addr));
}

__device__ __forceinline__ void mma_bf16(float* c, const uint32_t* a, uint32_t b0, uint32_t b1) {
    asm volatile("mma.sync.aligned.m16n8k16.row.col.f32.bf16.bf16.f32 "
                 "{%0,%1,%2,%3}, {%4,%5,%6,%7}, {%8,%9}, {%0,%1,%2,%3};"
                 : "+f"(c[0]), "+f"(c[1]), "+f"(c[2]), "+f"(c[3])
                 : "r"(a[0]), "r"(a[1]), "r"(a[2]), "r"(a[3]), "r"(b0), "r"(b1));
}

__device__ __forceinline__ void cp16(uint32_t dst, const void* src) {
    asm volatile("cp.async.cg.shared.global [%0], [%1], 16;" :: "r"(dst), "l"(src) : "memory");
}

__device__ __forceinline__ float sqrt_approx(float x) {
    float r;
    asm("sqrt.approx.f32 %0, %1;" : "=f"(r) : "f"(x));
    return r;
}
__device__ __forceinline__ float dist1(float xe, float c) {
    return sqrt_approx(fmaxf(fmaf(-2.0f, c, xe), 0.0f));
}

// logical col l (within 16-group) -> physical smem row, so that mma fragment
// ownership {2t, 2t+1, 2t+8, 2t+9} (phys) maps to logical {4t..4t+3}.
__device__ __forceinline__ int bperm(int l) {
    int t = l >> 2, j = l & 3;
    return 2 * t + (j & 1) + ((j >> 1) << 3);
}

// ---------------- merged prep: fp32 -> bf16 + exact fp32 row norms ----------------
__global__ __launch_bounds__(256)
void conv_all(const float* __restrict__ X, const float* __restrict__ E, int kblocks) {
    const int b    = blockIdx.x;
    const int tid  = threadIdx.x;
    const int lane = tid & 31;
    const float4* sv;
    __nv_bfloat16* drow;
    float* sqrow;
    if (b < kblocks) {
        sv    = reinterpret_cast<const float4*>(E) + (size_t)b * 2048;
        drow  = g_Ebf + (size_t)b * 8192;
        sqrow = g_esq + (size_t)b * 128;
    } else {
        const int c = b - kblocks;
        sv    = reinterpret_cast<const float4*>(X) + (size_t)c * 2048;
        drow  = g_Xbf + (size_t)c * 8192;
        sqrow = g_xsq + (size_t)c * 128;
    }
    #pragma unroll
    for (int i = 0; i < 8; i++) {
        const int f   = tid + i * 256;
        const int row = f >> 4;
        const int c4  = f & 15;
        float4 v = sv[f];
        float ss = v.x * v.x + v.y * v.y + v.z * v.z + v.w * v.w;
        __nv_bfloat162 p0 = __floats2bfloat162_rn(v.x, v.y);
        __nv_bfloat162 p1 = __floats2bfloat162_rn(v.z, v.w);
        uint2 pk;
        pk.x = *reinterpret_cast<uint32_t*>(&p0);
        pk.y = *reinterpret_cast<uint32_t*>(&p1);
        *reinterpret_cast<uint2*>(drow + row * 64 + c4 * 4) = pk;
        ss += __shfl_xor_sync(0xffffffffu, ss, 1);
        ss += __shfl_xor_sync(0xffffffffu, ss, 2);
        ss += __shfl_xor_sync(0xffffffffu, ss, 4);
        ss += __shfl_xor_sync(0xffffffffu, ss, 8);
        if ((lane & 15) == 0) sqrow[row] = ss;
    }
}

// ---------------- main ----------------
// per-warp A-slice load: 32 rows (4KB) + 32 norms (128B), 8 cp16/lane (+1 on lanes<8)
__device__ __forceinline__ void issue_Aw(uint32_t stg, int grow, int lane) {
    #pragma unroll
    for (int i = 0; i < 8; i++) {
        const int chunk = lane + i * 32;          // 256 chunks of 16B
        const int row   = chunk >> 3;             // 0..31
        const int c     = chunk & 7;
        cp16(stg + SWZ((uint32_t)(row * 128 + c * 16)),
             g_Xbf + (size_t)(grow + row) * 64 + c * 8);
    }
    if (lane < 8) cp16(stg + 4096 + lane * 16, g_xsq + grow + lane * 4);
    asm volatile("cp.async.commit_group;" ::: "memory");
}

__global__ __launch_bounds__(256, 2)
void vq_cdist_kernel(float* __restrict__ out, int Kdim, int nm, int nx) {
    extern __shared__ char smem[];
    const uint32_t s_base = (uint32_t)__cvta_generic_to_shared(smem);

    const int tid  = threadIdx.x;
    const int lane = tid & 31;
    const int wid  = tid >> 5;
    const int wm = (wid & 3) * 32;
    const int wn = (wid >> 2) * 32;

    const int group = blockIdx.x / nx;          // m-stripe group
    const int n0    = (blockIdx.x % nx) * BN;   // fixed n-tile for this CTA
    const int ng    = gridDim.x / nx;

    // ---- prologue: B tile + es once (plain LDG/STS), cooperative ----
    #pragma unroll
    for (int i = 0; i < 2; i++) {               // 512 chunks (64 rows x 128B)
        const int f    = tid + i * 256;
        const int lrow = f >> 3;
        const int c    = f & 7;
        const int prow = (lrow & ~15) | bperm(lrow & 15);
        const uint4 v = *reinterpret_cast<const uint4*>(
            g_Ebf + (size_t)(n0 + lrow) * 64 + c * 8);
        *reinterpret_cast<uint4*>(smem + SWZ((uint32_t)(prow * 128 + c * 16))) = v;
    }
    if (tid < 64) reinterpret_cast<float*>(smem + ES_OFF)[tid] = g_esq[n0 + tid];

    // per-warp A pipeline prologue (independent of B visibility)
    const uint32_t wst = s_base + WBASE + wid * WREG;
    issue_Aw(wst,           (group)      * BM + wm, lane);
    issue_Aw(wst + A_ST,    (group + ng) * BM + wm, lane);   // every group has >= 2 tiles

    __syncthreads();   // B + es visible to all warps

    // ---- persistent B fragments (32 regs) ----
    uint32_t bfr[4][2][4];
    #pragma unroll
    for (int ks = 0; ks < 4; ks++) {
        #pragma unroll
        for (int np = 0; np < 2; np++) {
            const int nr = wn + np * 16 + ((lane >> 4) & 1) * 8 + (lane & 7);
            const int kb = (ks * 16 + ((lane >> 3) & 1) * 8) * 2;
            ldsm_x4(bfr[ks][np][0], bfr[ks][np][1], bfr[ks][np][2], bfr[ks][np][3],
                    s_base + SWZ((uint32_t)(nr * 128 + kb)));
        }
    }
    const float* es_s = reinterpret_cast<const float*>(smem + ES_OFF);

    // ---- warp-autonomous main loop: NO barriers ----
    int st = 0;
    for (int mi = group; mi < nm; mi += ng) {
        const int mi2 = mi + 2 * ng;
        if (mi2 < nm) {
            const int st2 = (st == 0) ? 2 : st - 1;   // (st+2) % 3
            issue_Aw(wst + st2 * A_ST, mi2 * BM + wm, lane);
            asm volatile("cp.async.wait_group 2;" ::: "memory");
        } else if (mi + ng < nm) {
            asm volatile("cp.async.wait_group 1;" ::: "memory");
        } else {
            asm volatile("cp.async.wait_group 0;" ::: "memory");
        }

        const uint32_t a_base = wst + st * A_ST;
        const float* xs_s = reinterpret_cast<const float*>(
            smem + WBASE + wid * WREG + st * A_ST + 4096);
        const int m0 = mi * BM;

        float acc[2][4][4];
        #pragma unroll
        for (int mt = 0; mt < 2; mt++)
            #pragma unroll
            for (int nt = 0; nt < 4; nt++)
                #pragma unroll
                for (int i = 0; i < 4; i++) acc[mt][nt][i] = 0.f;

        #pragma unroll
        for (int ks = 0; ks < 4; ks++) {
            const int kc = ks * 16;
            uint32_t a_frag[2][4];
            #pragma unroll
            for (int mt = 0; mt < 2; mt++) {
                const int r  = mt * 16 + (lane & 15);            // local row 0..31
                const int cb = (kc + ((lane >> 4) << 3)) * 2;
                ldsm_x4(a_frag[mt][0], a_frag[mt][1], a_frag[mt][2], a_frag[mt][3],
                        a_base + SWZ((uint32_t)(r * 128 + cb)));
            }
            #pragma unroll
            for (int np = 0; np < 2; np++) {
                #pragma unroll
                for (int mt = 0; mt < 2; mt++) {
                    mma_bf16(acc[mt][np * 2],     a_frag[mt], bfr[ks][np][0], bfr[ks][np][1]);
                    mma_bf16(acc[mt][np * 2 + 1], a_frag[mt], bfr[ks][np][2], bfr[ks][np][3]);
                }
            }
        }

        // ---- epilogue: thread owns 4 contiguous logical cols per 16-group ----
        const int rl = (lane >> 2);               // local row base
        const int t4 = (lane & 3) * 4;
        #pragma unroll
        for (int mt = 0; mt < 2; mt++) {
            const int lr0 = rl + mt * 16;         // local rows within warp slice
            const int lr1 = lr0 + 8;
            const float xsa = xs_s[lr0];
            const float xsb = xs_s[lr1];
            float* o0 = out + (size_t)(m0 + wm + lr0) * Kdim + n0 + wn;
            float* o1 = out + (size_t)(m0 + wm + lr1) * Kdim + n0 + wn;
            #pragma unroll
            for (int q = 0; q < 2; q++) {
                const int c = q * 16 + t4;
                const float4 es = *reinterpret_cast<const float4*>(&es_s[wn + c]);
                float4 v0, v1;
                v0.x = dist1(xsa + es.x, acc[mt][2*q][0]);
                v0.y = dist1(xsa + es.y, acc[mt][2*q][1]);
                v0.z = dist1(xsa + es.z, acc[mt][2*q+1][0]);
                v0.w = dist1(xsa + es.w, acc[mt][2*q+1][1]);
                v1.x = dist1(xsb + es.x, acc[mt][2*q][2]);
                v1.y = dist1(xsb + es.y, acc[mt][2*q][3]);
                v1.z = dist1(xsb + es.z, acc[mt][2*q+1][2]);
                v1.w = dist1(xsb + es.w, acc[mt][2*q+1][3]);
                __stcs(reinterpret_cast<float4*>(o0 + c), v0);
                __stcs(reinterpret_cast<float4*>(o1 + c), v1);
            }
        }

        st = (st == 2) ? 0 : st + 1;
    }
}

extern "C" void kernel_launch(void* const* d_in, const int* in_sizes, int n_in,
                              void* d_out, int out_size) {
    const float* X = (const float*)d_in[0];   // inputs [N, 64]
    const float* E = (const float*)d_in[1];   // embeddings [K, 64]
    float* out = (float*)d_out;               // [N, K] fp32

    const int N = in_sizes[0] / 64;
    const int K = in_sizes[1] / 64;
    const int nx = K / BN;                    // 16
    const int nm = N / BM;                    // 512

    static int configured = 0;
    if (!configured) {
        cudaFuncSetAttribute(vq_cdist_kernel,
                             cudaFuncAttributeMaxDynamicSharedMemorySize, DYN_SMEM);
        configured = 1;
    }

    int sms = 148;
    cudaDeviceGetAttribute(&sms, cudaDevAttrMultiProcessorCount, 0);
    int grid = (2 * sms / nx) * nx;           // multiple of nx (304 on GB300)
    if (grid < nx) grid = nx;

    conv_all<<<K / 128 + N / 128, 256>>>(X, E, K / 128);
    vq_cdist_kernel<<<grid, 256, DYN_SMEM>>>(out, K, nm, nx);
}